// round 1
// baseline (speedup 1.0000x reference)
#include <cuda_runtime.h>
#include <math.h>

// ---------------------------------------------------------------------------
// Soft decision tree:
//   P = sigmoid(x @ W + b)          x:[B,K1] W:[K1,NODES] b:[NODES]
//   probs: per-row product over tree path (DEPTH levels -> LEAVES)
//   out  = probs @ value            value:[LEAVES,OUT_DIM]
//   reg  = sum_d -0.5*2^-d * sum_{nodes in d} mean_b log(max(p(1-p),1e-5))
// ---------------------------------------------------------------------------

#define B_ROWS   16384
#define IN_DIM   2048
#define N_NODES  1023
#define NPAD     1024
#define N_LEAVES 1024
#define OUT_DIM  512
#define DEPTH    10

// Scratch (allocation-free rule: __device__ globals)
__device__ float g_P[B_ROWS * NPAD];        // sigmoid probs, padded to 1024 cols
__device__ float g_probs[B_ROWS * N_LEAVES];
__device__ float g_partial[B_ROWS];         // per-row reg partials

// ---------------------------------------------------------------------------
// GEMM1: P = sigmoid(X @ W + b).  Tile 128x128, K-tile 16, 256 thr, 8x8/thr.
// W is [IN_DIM, N_NODES] row-major with stride 1023 (odd) -> scalar loads.
// ---------------------------------------------------------------------------
#define BM 128
#define BN 128
#define BK 16
#define TM 8
#define TN 8

__global__ __launch_bounds__(256)
void gemm1_sigmoid(const float* __restrict__ X, const float* __restrict__ W,
                   const float* __restrict__ bias, float* __restrict__ P)
{
    __shared__ __align__(16) float As[BK][BM];   // transposed A tile
    __shared__ __align__(16) float Bs[BK][BN];

    const int tid     = threadIdx.x;
    const int block_m = blockIdx.y * BM;
    const int block_n = blockIdx.x * BN;
    const int tm      = (tid / 16) * TM;
    const int tn      = (tid % 16) * TN;

    float acc[TM][TN];
    #pragma unroll
    for (int i = 0; i < TM; i++)
        #pragma unroll
        for (int j = 0; j < TN; j++) acc[i][j] = 0.f;

    for (int k0 = 0; k0 < IN_DIM; k0 += BK) {
        // --- load A tile: 128 rows x 16 cols = 512 float4, 2 per thread ---
        #pragma unroll
        for (int l = 0; l < 2; l++) {
            int e    = tid + l * 256;        // float4 index
            int arow = e >> 2;               // 4 float4 per row
            int acol = (e & 3) * 4;
            float4 v = *reinterpret_cast<const float4*>(
                &X[(size_t)(block_m + arow) * IN_DIM + k0 + acol]);
            As[acol + 0][arow] = v.x;
            As[acol + 1][arow] = v.y;
            As[acol + 2][arow] = v.z;
            As[acol + 3][arow] = v.w;
        }
        // --- load B tile: 16 rows x 128 cols, scalar (stride 1023), 8/thr ---
        #pragma unroll
        for (int l = 0; l < 8; l++) {
            int e    = tid + l * 256;
            int krow = e >> 7;
            int col  = e & 127;
            int n    = block_n + col;
            Bs[krow][col] = (n < N_NODES)
                ? W[(size_t)(k0 + krow) * N_NODES + n] : 0.f;
        }
        __syncthreads();

        #pragma unroll
        for (int kk = 0; kk < BK; kk++) {
            float regM[TM], regN[TN];
            float4 a0 = *reinterpret_cast<const float4*>(&As[kk][tm]);
            float4 a1 = *reinterpret_cast<const float4*>(&As[kk][tm + 4]);
            float4 b0 = *reinterpret_cast<const float4*>(&Bs[kk][tn]);
            float4 b1 = *reinterpret_cast<const float4*>(&Bs[kk][tn + 4]);
            regM[0]=a0.x; regM[1]=a0.y; regM[2]=a0.z; regM[3]=a0.w;
            regM[4]=a1.x; regM[5]=a1.y; regM[6]=a1.z; regM[7]=a1.w;
            regN[0]=b0.x; regN[1]=b0.y; regN[2]=b0.z; regN[3]=b0.w;
            regN[4]=b1.x; regN[5]=b1.y; regN[6]=b1.z; regN[7]=b1.w;
            #pragma unroll
            for (int i = 0; i < TM; i++)
                #pragma unroll
                for (int j = 0; j < TN; j++)
                    acc[i][j] = fmaf(regM[i], regN[j], acc[i][j]);
        }
        __syncthreads();
    }

    // epilogue: bias + sigmoid, store (padded col 1023 gets sigmoid(0+0)=0.5, unused)
    #pragma unroll
    for (int i = 0; i < TM; i++) {
        const int row = block_m + tm + i;
        float vals[TN];
        #pragma unroll
        for (int j = 0; j < TN; j++) {
            int n   = block_n + tn + j;
            float z = acc[i][j] + ((n < N_NODES) ? bias[n] : 0.f);
            vals[j] = 1.f / (1.f + expf(-z));
        }
        float4* dst = reinterpret_cast<float4*>(&P[(size_t)row * NPAD + block_n + tn]);
        dst[0] = make_float4(vals[0], vals[1], vals[2], vals[3]);
        dst[1] = make_float4(vals[4], vals[5], vals[6], vals[7]);
    }
}

// ---------------------------------------------------------------------------
// Tree kernel: one block per batch row. Computes leaf probs by level doubling
// in shared memory, and the per-row weighted-log reg partial.
// ---------------------------------------------------------------------------
__global__ __launch_bounds__(256)
void tree_probs(const float* __restrict__ P, float* __restrict__ probs,
                float* __restrict__ partial)
{
    __shared__ float buf[2][N_LEAVES];
    __shared__ float red[256];

    const int row = blockIdx.x;
    const int tid = threadIdx.x;
    const float* prow = P + (size_t)row * NPAD;

    if (tid == 0) buf[0][0] = 1.f;
    __syncthreads();

    float racc = 0.f;
    int cur = 0;
    #pragma unroll
    for (int d = 0; d < DEPTH; d++) {
        const int sz    = 1 << d;
        const int start = sz - 1;
        const float wd  = -0.5f / (float)sz;   // -0.5 * 2^-d
        for (int i = tid; i < sz; i += 256) {
            float p  = prow[start + i];
            float pc = buf[cur][i];
            buf[cur ^ 1][2 * i]     = pc * p;
            buf[cur ^ 1][2 * i + 1] = pc * (1.f - p);
            float q = p * (1.f - p);
            racc += wd * logf(fmaxf(q, 1e-5f));
        }
        __syncthreads();
        cur ^= 1;
    }

    for (int i = tid; i < N_LEAVES; i += 256)
        probs[(size_t)row * N_LEAVES + i] = buf[cur][i];

    red[tid] = racc;
    __syncthreads();
    #pragma unroll
    for (int s = 128; s > 0; s >>= 1) {
        if (tid < s) red[tid] += red[tid + s];
        __syncthreads();
    }
    if (tid == 0) partial[row] = red[0];
}

// ---------------------------------------------------------------------------
// GEMM2: out = probs @ value.  M=16384, N=512, K=1024. value stride 512 (f4 ok)
// ---------------------------------------------------------------------------
__global__ __launch_bounds__(256)
void gemm2(const float* __restrict__ A, const float* __restrict__ V,
           float* __restrict__ out)
{
    __shared__ __align__(16) float As[BK][BM];
    __shared__ __align__(16) float Bs[BK][BN];

    const int tid     = threadIdx.x;
    const int block_m = blockIdx.y * BM;
    const int block_n = blockIdx.x * BN;
    const int tm      = (tid / 16) * TM;
    const int tn      = (tid % 16) * TN;

    float acc[TM][TN];
    #pragma unroll
    for (int i = 0; i < TM; i++)
        #pragma unroll
        for (int j = 0; j < TN; j++) acc[i][j] = 0.f;

    for (int k0 = 0; k0 < N_LEAVES; k0 += BK) {
        #pragma unroll
        for (int l = 0; l < 2; l++) {
            int e    = tid + l * 256;
            int arow = e >> 2;
            int acol = (e & 3) * 4;
            float4 v = *reinterpret_cast<const float4*>(
                &A[(size_t)(block_m + arow) * N_LEAVES + k0 + acol]);
            As[acol + 0][arow] = v.x;
            As[acol + 1][arow] = v.y;
            As[acol + 2][arow] = v.z;
            As[acol + 3][arow] = v.w;
        }
        // B tile: 16 rows x 128 cols as float4 (32 f4/row -> 512 f4, 2/thr)
        #pragma unroll
        for (int l = 0; l < 2; l++) {
            int e     = tid + l * 256;
            int brow  = e >> 5;
            int bcol  = (e & 31) * 4;
            float4 v  = *reinterpret_cast<const float4*>(
                &V[(size_t)(k0 + brow) * OUT_DIM + block_n + bcol]);
            *reinterpret_cast<float4*>(&Bs[brow][bcol]) = v;
        }
        __syncthreads();

        #pragma unroll
        for (int kk = 0; kk < BK; kk++) {
            float regM[TM], regN[TN];
            float4 a0 = *reinterpret_cast<const float4*>(&As[kk][tm]);
            float4 a1 = *reinterpret_cast<const float4*>(&As[kk][tm + 4]);
            float4 b0 = *reinterpret_cast<const float4*>(&Bs[kk][tn]);
            float4 b1 = *reinterpret_cast<const float4*>(&Bs[kk][tn + 4]);
            regM[0]=a0.x; regM[1]=a0.y; regM[2]=a0.z; regM[3]=a0.w;
            regM[4]=a1.x; regM[5]=a1.y; regM[6]=a1.z; regM[7]=a1.w;
            regN[0]=b0.x; regN[1]=b0.y; regN[2]=b0.z; regN[3]=b0.w;
            regN[4]=b1.x; regN[5]=b1.y; regN[6]=b1.z; regN[7]=b1.w;
            #pragma unroll
            for (int i = 0; i < TM; i++)
                #pragma unroll
                for (int j = 0; j < TN; j++)
                    acc[i][j] = fmaf(regM[i], regN[j], acc[i][j]);
        }
        __syncthreads();
    }

    #pragma unroll
    for (int i = 0; i < TM; i++) {
        const int row = block_m + tm + i;
        float4* dst = reinterpret_cast<float4*>(&out[(size_t)row * OUT_DIM + block_n + tn]);
        dst[0] = make_float4(acc[i][0], acc[i][1], acc[i][2], acc[i][3]);
        dst[1] = make_float4(acc[i][4], acc[i][5], acc[i][6], acc[i][7]);
    }
}

// ---------------------------------------------------------------------------
// Final deterministic reduction of reg partials; writes scalar to out[idx].
// ---------------------------------------------------------------------------
__global__ __launch_bounds__(1024)
void reduce_reg(const float* __restrict__ partial, float* __restrict__ out_reg)
{
    __shared__ float red[1024];
    const int tid = threadIdx.x;
    float s = 0.f;
    for (int i = tid; i < B_ROWS; i += 1024) s += partial[i];
    red[tid] = s;
    __syncthreads();
    #pragma unroll
    for (int st = 512; st > 0; st >>= 1) {
        if (tid < st) red[tid] += red[tid + st];
        __syncthreads();
    }
    if (tid == 0) *out_reg = red[0] * (1.f / (float)B_ROWS);
}

// ---------------------------------------------------------------------------
extern "C" void kernel_launch(void* const* d_in, const int* in_sizes, int n_in,
                              void* d_out, int out_size)
{
    const float* x     = (const float*)d_in[0];
    const float* W     = (const float*)d_in[1];
    const float* bias  = (const float*)d_in[2];
    const float* value = (const float*)d_in[3];
    float* out = (float*)d_out;

    float *P, *probs, *partial;
    cudaGetSymbolAddress((void**)&P,       g_P);
    cudaGetSymbolAddress((void**)&probs,   g_probs);
    cudaGetSymbolAddress((void**)&partial, g_partial);

    // GEMM1 + sigmoid: grid (N tiles, M tiles)
    dim3 g1(NPAD / BN, B_ROWS / BM);
    gemm1_sigmoid<<<g1, 256>>>(x, W, bias, P);

    // tree probs + per-row reg partials
    tree_probs<<<B_ROWS, 256>>>(P, probs, partial);

    // GEMM2: out = probs @ value
    dim3 g2(OUT_DIM / BN, B_ROWS / BM);
    gemm2<<<g2, 256>>>(probs, value, out);

    // reg scalar -> last element of output buffer
    reduce_reg<<<1, 1024>>>(partial, out + (out_size - 1));
}

// round 7
// speedup vs baseline: 2.0546x; 2.0546x over previous
#include <cuda_runtime.h>
#include <cuda_bf16.h>
#include <math.h>
#include <stdint.h>

#define B_ROWS   16384
#define IN_DIM   2048
#define N_NODES  1023
#define NPAD     1024
#define N_LEAVES 1024
#define OUT_DIM  512
#define DEPTH    10

// ---------------- scratch (no allocs allowed) ----------------
__device__ __nv_bfloat16 g_Xhi[(size_t)B_ROWS * IN_DIM];
__device__ __nv_bfloat16 g_Xlo[(size_t)B_ROWS * IN_DIM];
__device__ __nv_bfloat16 g_WThi[(size_t)NPAD * IN_DIM];      // [node][k]
__device__ __nv_bfloat16 g_WTlo[(size_t)NPAD * IN_DIM];
__device__ __nv_bfloat16 g_VThi[(size_t)OUT_DIM * N_LEAVES]; // [out][leaf]
__device__ __nv_bfloat16 g_VTlo[(size_t)OUT_DIM * N_LEAVES];
__device__ float         g_P[(size_t)B_ROWS * NPAD];
__device__ __nv_bfloat16 g_PRhi[(size_t)B_ROWS * N_LEAVES];
__device__ __nv_bfloat16 g_PRlo[(size_t)B_ROWS * N_LEAVES];
__device__ float         g_partial[B_ROWS];

// ---------------- PTX helpers (compute_100 baseline only) ----------------
__device__ __forceinline__ uint32_t smem_u32(const void* p) {
    uint32_t a;
    asm("{ .reg .u64 t; cvta.to.shared.u64 t, %1; cvt.u32.u64 %0, t; }" : "=r"(a) : "l"(p));
    return a;
}
__device__ __forceinline__ void cp16(uint32_t dst, const void* src) {
    asm volatile("cp.async.cg.shared.global [%0], [%1], 16;" :: "r"(dst), "l"(src));
}
__device__ __forceinline__ void cp_commit() {
    asm volatile("cp.async.commit_group;" ::: "memory");
}
template <int N>
__device__ __forceinline__ void cp_wait() {
    asm volatile("cp.async.wait_group %0;" :: "n"(N) : "memory");
}
__device__ __forceinline__ void ldsm4(uint32_t* r, uint32_t addr) {
    asm volatile("ldmatrix.sync.aligned.m8n8.x4.shared.b16 {%0,%1,%2,%3}, [%4];"
                 : "=r"(r[0]), "=r"(r[1]), "=r"(r[2]), "=r"(r[3]) : "r"(addr));
}
__device__ __forceinline__ void mma16816(float* d, const uint32_t* a, uint32_t b0, uint32_t b1) {
    asm volatile(
        "mma.sync.aligned.m16n8k16.row.col.f32.bf16.bf16.f32 "
        "{%0,%1,%2,%3}, {%4,%5,%6,%7}, {%8,%9}, {%0,%1,%2,%3};"
        : "+f"(d[0]), "+f"(d[1]), "+f"(d[2]), "+f"(d[3])
        : "r"(a[0]), "r"(a[1]), "r"(a[2]), "r"(a[3]), "r"(b0), "r"(b1));
}

// ---------------- split-bf16 mma.sync GEMM ----------------
// C[M,N] = A[M,K] @ B[N,K]^T, A/B as bf16 hi/lo pairs, fp32 accum.
// CTA 128x128, BK=32, 8 warps (2M x 4N), warp tile 64x32, 3-stage cp.async.
// Both A and B are [row][k] with k contiguous -> NON-trans ldmatrix delivers
// the canonical row.col fragments for both operands.
#define BM 128
#define BN 128
#define BK 32
#define ROWB 80               // padded row stride in bytes (40 bf16)
#define PART_SZ (128 * ROWB)  // 10240 B: one operand part tile
#define STAGE_SZ (4 * PART_SZ)
#define STAGES 3
#define GEMM_SMEM (STAGES * STAGE_SZ)   // 122880

template <bool SIG>
__global__ void __launch_bounds__(256)
gemm_mma(const __nv_bfloat16* __restrict__ Ahi, const __nv_bfloat16* __restrict__ Alo,
         const __nv_bfloat16* __restrict__ Bhi, const __nv_bfloat16* __restrict__ Blo,
         const float* __restrict__ bias, float* __restrict__ C,
         int K, int ldc, int nvalid)
{
    extern __shared__ __align__(128) char smem[];
    const uint32_t sb = smem_u32(smem);
    const int tid = threadIdx.x, wid = tid >> 5, lane = tid & 31;
    const int wm = wid >> 2, wn = wid & 3;        // warp grid 2 x 4
    const int m0 = blockIdx.y * BM, n0 = blockIdx.x * BN;

    // per-thread cp.async pattern: 2 chunks per part. chunk c: row=c>>2, 16B col=c&3
    int c0r = tid >> 2,          c0c = (tid & 3) * 16;
    int c1r = (tid + 256) >> 2,  c1c = ((tid + 256) & 3) * 16;
    const size_t kb = (size_t)K * 2;  // row stride bytes in global
    const char* gAhi = (const char*)Ahi + (size_t)m0 * kb;
    const char* gAlo = (const char*)Alo + (size_t)m0 * kb;
    const char* gBhi = (const char*)Bhi + (size_t)n0 * kb;
    const char* gBlo = (const char*)Blo + (size_t)n0 * kb;

    auto load_stage = [&](int buf, int k0) {
        uint32_t base = sb + buf * STAGE_SZ;
        size_t ko = (size_t)k0 * 2;
        // part 0: Ahi, 1: Alo, 2: Bhi, 3: Blo
        cp16(base + c0r * ROWB + c0c,               gAhi + c0r * kb + ko + c0c);
        cp16(base + c1r * ROWB + c1c,               gAhi + c1r * kb + ko + c1c);
        cp16(base + PART_SZ + c0r * ROWB + c0c,     gAlo + c0r * kb + ko + c0c);
        cp16(base + PART_SZ + c1r * ROWB + c1c,     gAlo + c1r * kb + ko + c1c);
        cp16(base + 2*PART_SZ + c0r * ROWB + c0c,   gBhi + c0r * kb + ko + c0c);
        cp16(base + 2*PART_SZ + c1r * ROWB + c1c,   gBhi + c1r * kb + ko + c1c);
        cp16(base + 3*PART_SZ + c0r * ROWB + c0c,   gBlo + c0r * kb + ko + c0c);
        cp16(base + 3*PART_SZ + c1r * ROWB + c1c,   gBlo + c1r * kb + ko + c1c);
        cp_commit();
    };

    float acc[4][4][4];
#pragma unroll
    for (int i = 0; i < 4; i++)
#pragma unroll
        for (int j = 0; j < 4; j++)
#pragma unroll
            for (int q = 0; q < 4; q++) acc[i][j][q] = 0.f;

    const int ntiles = K / BK;
    load_stage(0, 0);
    load_stage(1, BK);

    const uint32_t lrow = (uint32_t)(lane & 15) * ROWB;
    const uint32_t lcol = (uint32_t)(lane >> 4) * 16;

    for (int kt = 0; kt < ntiles; kt++) {
        cp_wait<1>();
        __syncthreads();
        if (kt + 2 < ntiles) load_stage((kt + 2) % STAGES, (kt + 2) * BK);
        else cp_commit();   // keep group count flowing

        const uint32_t bufb = sb + (kt % STAGES) * STAGE_SZ;
#pragma unroll
        for (int ks = 0; ks < 2; ks++) {
            const uint32_t koff = ks * 32 + lcol;   // bytes within row
            uint32_t ahi[4][4], alo[4][4], bhi[2][4], blo[2][4];
#pragma unroll
            for (int mt = 0; mt < 4; mt++) {
                uint32_t ad = bufb + (uint32_t)(wm * 64 + mt * 16) * ROWB + lrow + koff;
                ldsm4(ahi[mt], ad);
                ldsm4(alo[mt], ad + PART_SZ);
            }
#pragma unroll
            for (int nb = 0; nb < 2; nb++) {
                uint32_t bd = bufb + 2 * PART_SZ +
                              (uint32_t)(wn * 32 + nb * 16) * ROWB + lrow + koff;
                ldsm4(bhi[nb], bd);           // non-trans: [n][k] storage
                ldsm4(blo[nb], bd + PART_SZ);
            }
#pragma unroll
            for (int mt = 0; mt < 4; mt++)
#pragma unroll
                for (int nb = 0; nb < 2; nb++)
#pragma unroll
                    for (int blk = 0; blk < 2; blk++) {
                        float* d = acc[mt][nb * 2 + blk];
                        uint32_t bh0 = bhi[nb][blk], bh1 = bhi[nb][blk + 2];
                        uint32_t bl0 = blo[nb][blk], bl1 = blo[nb][blk + 2];
                        mma16816(d, ahi[mt], bh0, bh1);   // hi*hi
                        mma16816(d, ahi[mt], bl0, bl1);   // hi*lo
                        mma16816(d, alo[mt], bh0, bh1);   // lo*hi
                    }
        }
        __syncthreads();
    }

    // epilogue
#pragma unroll
    for (int mt = 0; mt < 4; mt++) {
        const int r = m0 + wm * 64 + mt * 16 + (lane >> 2);
#pragma unroll
        for (int nt = 0; nt < 4; nt++) {
            const int cb = n0 + wn * 32 + nt * 8 + (lane & 3) * 2;
            float v0 = acc[mt][nt][0], v1 = acc[mt][nt][1];
            float v2 = acc[mt][nt][2], v3 = acc[mt][nt][3];
            if (SIG) {
                float b0 = (cb     < nvalid) ? bias[cb]     : 0.f;
                float b1 = (cb + 1 < nvalid) ? bias[cb + 1] : 0.f;
                v0 = 1.f / (1.f + expf(-(v0 + b0)));
                v1 = 1.f / (1.f + expf(-(v1 + b1)));
                v2 = 1.f / (1.f + expf(-(v2 + b0)));
                v3 = 1.f / (1.f + expf(-(v3 + b1)));
            }
            *(float2*)(C + (size_t)r * ldc + cb)       = make_float2(v0, v1);
            *(float2*)(C + (size_t)(r + 8) * ldc + cb) = make_float2(v2, v3);
        }
    }
}

// ---------------- conversions ----------------
__global__ __launch_bounds__(256)
void conv_split(const float* __restrict__ src, __nv_bfloat16* __restrict__ hi,
                __nv_bfloat16* __restrict__ lo, int n4)
{
    int i = blockIdx.x * blockDim.x + threadIdx.x;
    if (i >= n4) return;
    float4 v = ((const float4*)src)[i];
    __nv_bfloat16 h0 = __float2bfloat16(v.x), h1 = __float2bfloat16(v.y);
    __nv_bfloat16 h2 = __float2bfloat16(v.z), h3 = __float2bfloat16(v.w);
    __nv_bfloat16 l0 = __float2bfloat16(v.x - __bfloat162float(h0));
    __nv_bfloat16 l1 = __float2bfloat16(v.y - __bfloat162float(h1));
    __nv_bfloat16 l2 = __float2bfloat16(v.z - __bfloat162float(h2));
    __nv_bfloat16 l3 = __float2bfloat16(v.w - __bfloat162float(h3));
    ((__nv_bfloat162*)hi)[2*i]   = __nv_bfloat162(h0, h1);
    ((__nv_bfloat162*)hi)[2*i+1] = __nv_bfloat162(h2, h3);
    ((__nv_bfloat162*)lo)[2*i]   = __nv_bfloat162(l0, l1);
    ((__nv_bfloat162*)lo)[2*i+1] = __nv_bfloat162(l2, l3);
}

// transpose + split: src [K][Nv] (row stride ld) -> dst [n][k]
__global__ __launch_bounds__(256)
void conv_T(const float* __restrict__ src, int ld, int K, int Nv,
            __nv_bfloat16* __restrict__ dhi, __nv_bfloat16* __restrict__ dlo)
{
    __shared__ float t[32][33];
    const int kb = blockIdx.y * 32, nb = blockIdx.x * 32;
    const int tx = threadIdx.x, ty = threadIdx.y;   // 32 x 8
    for (int r = ty; r < 32; r += 8) {
        int k = kb + r, n = nb + tx;
        t[r][tx] = (n < Nv) ? src[(size_t)k * ld + n] : 0.f;
    }
    __syncthreads();
    for (int r = ty; r < 32; r += 8) {
        int n = nb + r, k = kb + tx;
        float v = t[tx][r];
        __nv_bfloat16 h = __float2bfloat16(v);
        dhi[(size_t)n * K + k] = h;
        dlo[(size_t)n * K + k] = __float2bfloat16(v - __bfloat162float(h));
    }
}

// ---------------- tree kernel ----------------
__global__ __launch_bounds__(256)
void tree_probs(const float* __restrict__ P, __nv_bfloat16* __restrict__ phi,
                __nv_bfloat16* __restrict__ plo, float* __restrict__ partial)
{
    __shared__ float buf[2][N_LEAVES];
    __shared__ float red[256];

    const int row = blockIdx.x;
    const int tid = threadIdx.x;
    const float* prow = P + (size_t)row * NPAD;

    if (tid == 0) buf[0][0] = 1.f;
    __syncthreads();

    float racc = 0.f;
    int cur = 0;
#pragma unroll
    for (int d = 0; d < DEPTH; d++) {
        const int sz    = 1 << d;
        const int start = sz - 1;
        const float wd  = -0.5f / (float)sz;
        for (int i = tid; i < sz; i += 256) {
            float p  = prow[start + i];
            float pc = buf[cur][i];
            buf[cur ^ 1][2 * i]     = pc * p;
            buf[cur ^ 1][2 * i + 1] = pc * (1.f - p);
            float q = p * (1.f - p);
            racc += wd * logf(fmaxf(q, 1e-5f));
        }
        __syncthreads();
        cur ^= 1;
    }

    for (int i = tid; i < N_LEAVES; i += 256) {
        float v = buf[cur][i];
        __nv_bfloat16 h = __float2bfloat16(v);
        phi[(size_t)row * N_LEAVES + i] = h;
        plo[(size_t)row * N_LEAVES + i] = __float2bfloat16(v - __bfloat162float(h));
    }

    red[tid] = racc;
    __syncthreads();
#pragma unroll
    for (int s = 128; s > 0; s >>= 1) {
        if (tid < s) red[tid] += red[tid + s];
        __syncthreads();
    }
    if (tid == 0) partial[row] = red[0];
}

// ---------------- reg reduction ----------------
__global__ __launch_bounds__(1024)
void reduce_reg(const float* __restrict__ partial, float* __restrict__ out_reg)
{
    __shared__ float red[1024];
    const int tid = threadIdx.x;
    float s = 0.f;
    for (int i = tid; i < B_ROWS; i += 1024) s += partial[i];
    red[tid] = s;
    __syncthreads();
#pragma unroll
    for (int st = 512; st > 0; st >>= 1) {
        if (tid < st) red[tid] += red[tid + st];
        __syncthreads();
    }
    if (tid == 0) *out_reg = red[0] * (1.f / (float)B_ROWS);
}

// ---------------- launch ----------------
extern "C" void kernel_launch(void* const* d_in, const int* in_sizes, int n_in,
                              void* d_out, int out_size)
{
    const float* x     = (const float*)d_in[0];
    const float* W     = (const float*)d_in[1];
    const float* bias  = (const float*)d_in[2];
    const float* value = (const float*)d_in[3];
    float* out = (float*)d_out;

    __nv_bfloat16 *Xhi, *Xlo, *WThi, *WTlo, *VThi, *VTlo, *PRhi, *PRlo;
    float *P, *partial;
    cudaGetSymbolAddress((void**)&Xhi,  g_Xhi);
    cudaGetSymbolAddress((void**)&Xlo,  g_Xlo);
    cudaGetSymbolAddress((void**)&WThi, g_WThi);
    cudaGetSymbolAddress((void**)&WTlo, g_WTlo);
    cudaGetSymbolAddress((void**)&VThi, g_VThi);
    cudaGetSymbolAddress((void**)&VTlo, g_VTlo);
    cudaGetSymbolAddress((void**)&PRhi, g_PRhi);
    cudaGetSymbolAddress((void**)&PRlo, g_PRlo);
    cudaGetSymbolAddress((void**)&P,       g_P);
    cudaGetSymbolAddress((void**)&partial, g_partial);

    cudaFuncSetAttribute(gemm_mma<true>,
                         cudaFuncAttributeMaxDynamicSharedMemorySize, GEMM_SMEM);
    cudaFuncSetAttribute(gemm_mma<false>,
                         cudaFuncAttributeMaxDynamicSharedMemorySize, GEMM_SMEM);

    // 1. split-convert X
    conv_split<<<(B_ROWS * IN_DIM / 4 + 255) / 256, 256>>>(x, Xhi, Xlo, B_ROWS * IN_DIM / 4);
    // 2. transpose-convert W  [2048][1023] -> [1024][2048] (row 1023 zero)
    conv_T<<<dim3(NPAD / 32, IN_DIM / 32), dim3(32, 8)>>>(W, N_NODES, IN_DIM, N_NODES, WThi, WTlo);
    // 3. transpose-convert value [1024][512] -> [512][1024]
    conv_T<<<dim3(OUT_DIM / 32, N_LEAVES / 32), dim3(32, 8)>>>(value, OUT_DIM, N_LEAVES, OUT_DIM, VThi, VTlo);

    // 4. GEMM1 + bias + sigmoid -> P
    gemm_mma<true><<<dim3(NPAD / BN, B_ROWS / BM), 256, GEMM_SMEM>>>(
        Xhi, Xlo, WThi, WTlo, bias, P, IN_DIM, NPAD, N_NODES);

    // 5. tree probs (bf16 hi/lo) + reg partials
    tree_probs<<<B_ROWS, 256>>>(P, PRhi, PRlo, partial);

    // 6. GEMM2 -> out
    gemm_mma<false><<<dim3(OUT_DIM / BN, B_ROWS / BM), 256, GEMM_SMEM>>>(
        PRhi, PRlo, VThi, VTlo, nullptr, out, N_LEAVES, OUT_DIM, OUT_DIM);

    // 7. reg scalar
    reduce_reg<<<1, 1024>>>(partial, out + (out_size - 1));
}

// round 10
// speedup vs baseline: 2.3597x; 1.1485x over previous
#include <cuda_runtime.h>
#include <cuda_bf16.h>
#include <math.h>
#include <stdint.h>

#define B_ROWS   16384
#define IN_DIM   2048
#define N_NODES  1023
#define NPAD     1024
#define N_LEAVES 1024
#define OUT_DIM  512
#define DEPTH    10

// ---------------- scratch (no allocs allowed) ----------------
__device__ __nv_bfloat16 g_Xhi[(size_t)B_ROWS * IN_DIM];
__device__ __nv_bfloat16 g_Xlo[(size_t)B_ROWS * IN_DIM];
__device__ __nv_bfloat16 g_WThi[(size_t)NPAD * IN_DIM];      // [node][k]
__device__ __nv_bfloat16 g_WTlo[(size_t)NPAD * IN_DIM];
__device__ __nv_bfloat16 g_VThi[(size_t)OUT_DIM * N_LEAVES]; // [out][leaf]
__device__ __nv_bfloat16 g_VTlo[(size_t)OUT_DIM * N_LEAVES];
__device__ float         g_P[(size_t)B_ROWS * NPAD];
__device__ __nv_bfloat16 g_PRhi[(size_t)B_ROWS * N_LEAVES];
__device__ __nv_bfloat16 g_PRlo[(size_t)B_ROWS * N_LEAVES];
__device__ float         g_partial[B_ROWS];

// ---------------- PTX helpers (compute_100 baseline only) ----------------
__device__ __forceinline__ uint32_t smem_u32(const void* p) {
    uint32_t a;
    asm("{ .reg .u64 t; cvta.to.shared.u64 t, %1; cvt.u32.u64 %0, t; }" : "=r"(a) : "l"(p));
    return a;
}
__device__ __forceinline__ void cp16(uint32_t dst, const void* src) {
    asm volatile("cp.async.cg.shared.global [%0], [%1], 16;" :: "r"(dst), "l"(src));
}
__device__ __forceinline__ void cp_commit() {
    asm volatile("cp.async.commit_group;" ::: "memory");
}
template <int N>
__device__ __forceinline__ void cp_wait() {
    asm volatile("cp.async.wait_group %0;" :: "n"(N) : "memory");
}
__device__ __forceinline__ void ldsm4(uint32_t* r, uint32_t addr) {
    asm volatile("ldmatrix.sync.aligned.m8n8.x4.shared.b16 {%0,%1,%2,%3}, [%4];"
                 : "=r"(r[0]), "=r"(r[1]), "=r"(r[2]), "=r"(r[3]) : "r"(addr));
}
__device__ __forceinline__ void mma16816(float* d, const uint32_t* a, uint32_t b0, uint32_t b1) {
    asm volatile(
        "mma.sync.aligned.m16n8k16.row.col.f32.bf16.bf16.f32 "
        "{%0,%1,%2,%3}, {%4,%5,%6,%7}, {%8,%9}, {%0,%1,%2,%3};"
        : "+f"(d[0]), "+f"(d[1]), "+f"(d[2]), "+f"(d[3])
        : "r"(a[0]), "r"(a[1]), "r"(a[2]), "r"(a[3]), "r"(b0), "r"(b1));
}

// ---------------- split-bf16 mma.sync GEMM ----------------
// C[M,N] = A[M,K] @ B[N,K]^T, A/B as bf16 hi/lo pairs, fp32 accum.
// CTA 128x128, BK=32, 8 warps (2M x 4N), warp tile 64x32.
// 2-stage cp.async + 2 CTAs/SM (16 warps) for latency/sync hiding.
#define BM 128
#define BN 128
#define BK 32
#define ROWB 80               // padded row stride in bytes (40 bf16)
#define PART_SZ (128 * ROWB)  // 10240 B: one operand part tile
#define STAGE_SZ (4 * PART_SZ)
#define STAGES 2
#define GEMM_SMEM (STAGES * STAGE_SZ)   // 81920 -> 2 CTAs/SM

template <bool SIG>
__global__ void __launch_bounds__(256, 2)
gemm_mma(const __nv_bfloat16* __restrict__ Ahi, const __nv_bfloat16* __restrict__ Alo,
         const __nv_bfloat16* __restrict__ Bhi, const __nv_bfloat16* __restrict__ Blo,
         const float* __restrict__ bias, float* __restrict__ C,
         int K, int ldc, int nvalid)
{
    extern __shared__ __align__(128) char smem[];
    const uint32_t sb = smem_u32(smem);
    const int tid = threadIdx.x, wid = tid >> 5, lane = tid & 31;
    const int wm = wid >> 2, wn = wid & 3;        // warp grid 2 x 4
    const int m0 = blockIdx.y * BM, n0 = blockIdx.x * BN;

    // per-thread cp.async pattern: 2 chunks per part. chunk c: row=c>>2, 16B col=c&3
    int c0r = tid >> 2,          c0c = (tid & 3) * 16;
    int c1r = (tid + 256) >> 2,  c1c = ((tid + 256) & 3) * 16;
    const size_t kb = (size_t)K * 2;  // row stride bytes in global
    const char* gAhi = (const char*)Ahi + (size_t)m0 * kb;
    const char* gAlo = (const char*)Alo + (size_t)m0 * kb;
    const char* gBhi = (const char*)Bhi + (size_t)n0 * kb;
    const char* gBlo = (const char*)Blo + (size_t)n0 * kb;

    auto load_stage = [&](int buf, int k0) {
        uint32_t base = sb + buf * STAGE_SZ;
        size_t ko = (size_t)k0 * 2;
        // part 0: Ahi, 1: Alo, 2: Bhi, 3: Blo
        cp16(base + c0r * ROWB + c0c,               gAhi + c0r * kb + ko + c0c);
        cp16(base + c1r * ROWB + c1c,               gAhi + c1r * kb + ko + c1c);
        cp16(base + PART_SZ + c0r * ROWB + c0c,     gAlo + c0r * kb + ko + c0c);
        cp16(base + PART_SZ + c1r * ROWB + c1c,     gAlo + c1r * kb + ko + c1c);
        cp16(base + 2*PART_SZ + c0r * ROWB + c0c,   gBhi + c0r * kb + ko + c0c);
        cp16(base + 2*PART_SZ + c1r * ROWB + c1c,   gBhi + c1r * kb + ko + c1c);
        cp16(base + 3*PART_SZ + c0r * ROWB + c0c,   gBlo + c0r * kb + ko + c0c);
        cp16(base + 3*PART_SZ + c1r * ROWB + c1c,   gBlo + c1r * kb + ko + c1c);
        cp_commit();
    };

    float acc[4][4][4];
#pragma unroll
    for (int i = 0; i < 4; i++)
#pragma unroll
        for (int j = 0; j < 4; j++)
#pragma unroll
            for (int q = 0; q < 4; q++) acc[i][j][q] = 0.f;

    const int ntiles = K / BK;
    load_stage(0, 0);
    load_stage(1, BK);

    const uint32_t lrow = (uint32_t)(lane & 15) * ROWB;
    const uint32_t lcol = (uint32_t)(lane >> 4) * 16;
    const uint32_t a_off = (uint32_t)(wm * 64) * ROWB + lrow;
    const uint32_t b_off = 2 * PART_SZ + (uint32_t)(wn * 32) * ROWB + lrow;

    for (int kt = 0; kt < ntiles; kt++) {
        cp_wait<1>();            // stage kt resident
        __syncthreads();

        const uint32_t bufb = sb + (kt & 1) * STAGE_SZ;
#pragma unroll
        for (int ks = 0; ks < 2; ks++) {
            const uint32_t koff = ks * 32 + lcol;   // bytes within row
            uint32_t ahi[4][4], alo[4][4], bhi[2][4], blo[2][4];
#pragma unroll
            for (int mt = 0; mt < 4; mt++) {
                uint32_t ad = bufb + a_off + (uint32_t)(mt * 16) * ROWB + koff;
                ldsm4(ahi[mt], ad);
                ldsm4(alo[mt], ad + PART_SZ);
            }
#pragma unroll
            for (int nb = 0; nb < 2; nb++) {
                uint32_t bd = bufb + b_off + (uint32_t)(nb * 16) * ROWB + koff;
                ldsm4(bhi[nb], bd);
                ldsm4(blo[nb], bd + PART_SZ);
            }
            // product-major: 16 independent mma between reuses of each acc
#pragma unroll
            for (int mt = 0; mt < 4; mt++)
#pragma unroll
                for (int nb = 0; nb < 2; nb++)
#pragma unroll
                    for (int blk = 0; blk < 2; blk++)
                        mma16816(acc[mt][nb * 2 + blk], ahi[mt],
                                 bhi[nb][blk], bhi[nb][blk + 2]);
#pragma unroll
            for (int mt = 0; mt < 4; mt++)
#pragma unroll
                for (int nb = 0; nb < 2; nb++)
#pragma unroll
                    for (int blk = 0; blk < 2; blk++)
                        mma16816(acc[mt][nb * 2 + blk], ahi[mt],
                                 blo[nb][blk], blo[nb][blk + 2]);
#pragma unroll
            for (int mt = 0; mt < 4; mt++)
#pragma unroll
                for (int nb = 0; nb < 2; nb++)
#pragma unroll
                    for (int blk = 0; blk < 2; blk++)
                        mma16816(acc[mt][nb * 2 + blk], alo[mt],
                                 bhi[nb][blk], bhi[nb][blk + 2]);
        }
        __syncthreads();         // all warps done reading buf (kt&1)
        if (kt + 2 < ntiles) load_stage(kt & 1, (kt + 2) * BK);
        else cp_commit();        // keep group accounting for cp_wait<1>
    }

    // epilogue
#pragma unroll
    for (int mt = 0; mt < 4; mt++) {
        const int r = m0 + wm * 64 + mt * 16 + (lane >> 2);
#pragma unroll
        for (int nt = 0; nt < 4; nt++) {
            const int cb = n0 + wn * 32 + nt * 8 + (lane & 3) * 2;
            float v0 = acc[mt][nt][0], v1 = acc[mt][nt][1];
            float v2 = acc[mt][nt][2], v3 = acc[mt][nt][3];
            if (SIG) {
                float b0 = (cb     < nvalid) ? bias[cb]     : 0.f;
                float b1 = (cb + 1 < nvalid) ? bias[cb + 1] : 0.f;
                v0 = 1.f / (1.f + expf(-(v0 + b0)));
                v1 = 1.f / (1.f + expf(-(v1 + b1)));
                v2 = 1.f / (1.f + expf(-(v2 + b0)));
                v3 = 1.f / (1.f + expf(-(v3 + b1)));
            }
            *(float2*)(C + (size_t)r * ldc + cb)       = make_float2(v0, v1);
            *(float2*)(C + (size_t)(r + 8) * ldc + cb) = make_float2(v2, v3);
        }
    }
}

// ---------------- conversions ----------------
__global__ __launch_bounds__(256)
void conv_split(const float* __restrict__ src, __nv_bfloat16* __restrict__ hi,
                __nv_bfloat16* __restrict__ lo, int n4)
{
    int i = blockIdx.x * blockDim.x + threadIdx.x;
    if (i >= n4) return;
    float4 v = ((const float4*)src)[i];
    __nv_bfloat16 h0 = __float2bfloat16(v.x), h1 = __float2bfloat16(v.y);
    __nv_bfloat16 h2 = __float2bfloat16(v.z), h3 = __float2bfloat16(v.w);
    __nv_bfloat16 l0 = __float2bfloat16(v.x - __bfloat162float(h0));
    __nv_bfloat16 l1 = __float2bfloat16(v.y - __bfloat162float(h1));
    __nv_bfloat16 l2 = __float2bfloat16(v.z - __bfloat162float(h2));
    __nv_bfloat16 l3 = __float2bfloat16(v.w - __bfloat162float(h3));
    ((__nv_bfloat162*)hi)[2*i]   = __nv_bfloat162(h0, h1);
    ((__nv_bfloat162*)hi)[2*i+1] = __nv_bfloat162(h2, h3);
    ((__nv_bfloat162*)lo)[2*i]   = __nv_bfloat162(l0, l1);
    ((__nv_bfloat162*)lo)[2*i+1] = __nv_bfloat162(l2, l3);
}

// transpose + split: src [K][Nv] (row stride ld) -> dst [n][k]
__global__ __launch_bounds__(256)
void conv_T(const float* __restrict__ src, int ld, int K, int Nv,
            __nv_bfloat16* __restrict__ dhi, __nv_bfloat16* __restrict__ dlo)
{
    __shared__ float t[32][33];
    const int kb = blockIdx.y * 32, nb = blockIdx.x * 32;
    const int tx = threadIdx.x, ty = threadIdx.y;   // 32 x 8
    for (int r = ty; r < 32; r += 8) {
        int k = kb + r, n = nb + tx;
        t[r][tx] = (n < Nv) ? src[(size_t)k * ld + n] : 0.f;
    }
    __syncthreads();
    for (int r = ty; r < 32; r += 8) {
        int n = nb + r, k = kb + tx;
        float v = t[tx][r];
        __nv_bfloat16 h = __float2bfloat16(v);
        dhi[(size_t)n * K + k] = h;
        dlo[(size_t)n * K + k] = __float2bfloat16(v - __bfloat162float(h));
    }
}

// ---------------- tree kernel ----------------
__global__ __launch_bounds__(256)
void tree_probs(const float* __restrict__ P, __nv_bfloat16* __restrict__ phi,
                __nv_bfloat16* __restrict__ plo, float* __restrict__ partial)
{
    __shared__ float buf[2][N_LEAVES];
    __shared__ float red[256];

    const int row = blockIdx.x;
    const int tid = threadIdx.x;
    const float* prow = P + (size_t)row * NPAD;

    if (tid == 0) buf[0][0] = 1.f;
    __syncthreads();

    float racc = 0.f;
    int cur = 0;
#pragma unroll
    for (int d = 0; d < DEPTH; d++) {
        const int sz    = 1 << d;
        const int start = sz - 1;
        const float wd  = -0.5f / (float)sz;
        for (int i = tid; i < sz; i += 256) {
            float p  = prow[start + i];
            float pc = buf[cur][i];
            buf[cur ^ 1][2 * i]     = pc * p;
            buf[cur ^ 1][2 * i + 1] = pc * (1.f - p);
            float q = p * (1.f - p);
            racc += wd * logf(fmaxf(q, 1e-5f));
        }
        __syncthreads();
        cur ^= 1;
    }

    for (int i = tid; i < N_LEAVES; i += 256) {
        float v = buf[cur][i];
        __nv_bfloat16 h = __float2bfloat16(v);
        phi[(size_t)row * N_LEAVES + i] = h;
        plo[(size_t)row * N_LEAVES + i] = __float2bfloat16(v - __bfloat162float(h));
    }

    red[tid] = racc;
    __syncthreads();
#pragma unroll
    for (int s = 128; s > 0; s >>= 1) {
        if (tid < s) red[tid] += red[tid + s];
        __syncthreads();
    }
    if (tid == 0) partial[row] = red[0];
}

// ---------------- reg reduction ----------------
__global__ __launch_bounds__(1024)
void reduce_reg(const float* __restrict__ partial, float* __restrict__ out_reg)
{
    __shared__ float red[1024];
    const int tid = threadIdx.x;
    float s = 0.f;
    for (int i = tid; i < B_ROWS; i += 1024) s += partial[i];
    red[tid] = s;
    __syncthreads();
#pragma unroll
    for (int st = 512; st > 0; st >>= 1) {
        if (tid < st) red[tid] += red[tid + st];
        __syncthreads();
    }
    if (tid == 0) *out_reg = red[0] * (1.f / (float)B_ROWS);
}

// ---------------- launch ----------------
extern "C" void kernel_launch(void* const* d_in, const int* in_sizes, int n_in,
                              void* d_out, int out_size)
{
    const float* x     = (const float*)d_in[0];
    const float* W     = (const float*)d_in[1];
    const float* bias  = (const float*)d_in[2];
    const float* value = (const float*)d_in[3];
    float* out = (float*)d_out;

    __nv_bfloat16 *Xhi, *Xlo, *WThi, *WTlo, *VThi, *VTlo, *PRhi, *PRlo;
    float *P, *partial;
    cudaGetSymbolAddress((void**)&Xhi,  g_Xhi);
    cudaGetSymbolAddress((void**)&Xlo,  g_Xlo);
    cudaGetSymbolAddress((void**)&WThi, g_WThi);
    cudaGetSymbolAddress((void**)&WTlo, g_WTlo);
    cudaGetSymbolAddress((void**)&VThi, g_VThi);
    cudaGetSymbolAddress((void**)&VTlo, g_VTlo);
    cudaGetSymbolAddress((void**)&PRhi, g_PRhi);
    cudaGetSymbolAddress((void**)&PRlo, g_PRlo);
    cudaGetSymbolAddress((void**)&P,       g_P);
    cudaGetSymbolAddress((void**)&partial, g_partial);

    cudaFuncSetAttribute(gemm_mma<true>,
                         cudaFuncAttributeMaxDynamicSharedMemorySize, GEMM_SMEM);
    cudaFuncSetAttribute(gemm_mma<false>,
                         cudaFuncAttributeMaxDynamicSharedMemorySize, GEMM_SMEM);

    // 1. split-convert X
    conv_split<<<(B_ROWS * IN_DIM / 4 + 255) / 256, 256>>>(x, Xhi, Xlo, B_ROWS * IN_DIM / 4);
    // 2. transpose-convert W  [2048][1023] -> [1024][2048] (row 1023 zero)
    conv_T<<<dim3(NPAD / 32, IN_DIM / 32), dim3(32, 8)>>>(W, N_NODES, IN_DIM, N_NODES, WThi, WTlo);
    // 3. transpose-convert value [1024][512] -> [512][1024]
    conv_T<<<dim3(OUT_DIM / 32, N_LEAVES / 32), dim3(32, 8)>>>(value, OUT_DIM, N_LEAVES, OUT_DIM, VThi, VTlo);

    // 4. GEMM1 + bias + sigmoid -> P
    gemm_mma<true><<<dim3(NPAD / BN, B_ROWS / BM), 256, GEMM_SMEM>>>(
        Xhi, Xlo, WThi, WTlo, bias, P, IN_DIM, NPAD, N_NODES);

    // 5. tree probs (bf16 hi/lo) + reg partials
    tree_probs<<<B_ROWS, 256>>>(P, PRhi, PRlo, partial);

    // 6. GEMM2 -> out
    gemm_mma<false><<<dim3(OUT_DIM / BN, B_ROWS / BM), 256, GEMM_SMEM>>>(
        PRhi, PRlo, VThi, VTlo, nullptr, out, N_LEAVES, OUT_DIM, OUT_DIM);

    // 7. reg scalar
    reduce_reg<<<1, 1024>>>(partial, out + (out_size - 1));
}